// round 1
// baseline (speedup 1.0000x reference)
#include <cuda_runtime.h>
#include <math.h>

// Problem constants
#define BN 16
#define NB 1024
#define NS 4096
#define CC 768
#define HH 12
#define DH 64
#define TK 128
#define CH 3072

// Scratch: one big device-global buffer (no allocations allowed).
// layout (floats):
//   q       : [16384,768]   at 0
//   k       : [2048,768]    at 12582912
//   v       : [2048,768]    at 14155776
//   attended: [16384,768]   at 15728640
//   s2      : [16384,768]   at 28311552
//   x1      : [16384,768]   at 40894464
//   h       : [16384,3072]  at 53477376  (ends 103809024)
__device__ float g_buf[103809024];

static const long OFF_K   = 12582912;
static const long OFF_V   = 14155776;
static const long OFF_ATT = 15728640;
static const long OFF_S2  = 28311552;
static const long OFF_X1  = 40894464;
static const long OFF_H   = 53477376;

__device__ __forceinline__ void atomicMaxF(float* addr, float v) {
    int* ai = (int*)addr;
    int old = *ai;
    while (__int_as_float(old) < v) {
        int prev = atomicCAS(ai, old, __float_as_int(v));
        if (prev == old) break;
        old = prev;
    }
}

__device__ __forceinline__ float gelu_exact(float x) {
    return 0.5f * x * (1.0f + erff(x * 0.70710678118654752440f));
}

// ---------------------------------------------------------------------------
// fill scores with -inf
// ---------------------------------------------------------------------------
__global__ void fill_neg_inf(float* __restrict__ p, int n) {
    int i = blockIdx.x * blockDim.x + threadIdx.x;
    if (i < n) p[i] = __int_as_float(0xff800000);
}

// ---------------------------------------------------------------------------
// Generic SGEMM: C[M,N] = A[M,K] * op(B) (+bias, +gelu, or row-max epilogue)
//   TRANSB=false: B is [K,N] row-major
//   TRANSB=true : B is [N,K] row-major (C = A * B^T)
//   EPI: 0 = store acc+bias; 1 = store gelu(acc+bias); 2 = row-max*scale -> atomicMax (no store)
// Tiles: 128x128x16, 256 threads, 8x8 per thread. Dims must be multiples of tiles.
// ---------------------------------------------------------------------------
template<bool TRANSB, int EPI>
__global__ __launch_bounds__(256) void sgemm_kernel(
    const float* __restrict__ A, const float* __restrict__ Bm,
    const float* __restrict__ bias, float* __restrict__ Cm,
    int N, int Kd, long sA, long sB,
    float scale, float* __restrict__ rowmax, int rmStride)
{
    __shared__ float As[16 * 128];
    __shared__ float Bs[16 * 128];

    const int tid = threadIdx.x;
    const int tx = tid & 15, ty = tid >> 4;
    const int i0 = blockIdx.y * 128, j0 = blockIdx.x * 128;
    const float* Ab = A  + (long)blockIdx.z * sA;
    const float* Bb = Bm + (long)blockIdx.z * sB;

    float acc[8][8];
#pragma unroll
    for (int i = 0; i < 8; i++)
#pragma unroll
        for (int j = 0; j < 8; j++) acc[i][j] = 0.0f;

    for (int kt = 0; kt < Kd; kt += 16) {
        // Load A tile (transpose into As[k][m])
#pragma unroll
        for (int s = 0; s < 2; s++) {
            int f = tid + 256 * s;
            int r = f >> 2, c4 = f & 3;
            float4 v = *(const float4*)(Ab + (long)(i0 + r) * Kd + kt + c4 * 4);
            As[(c4 * 4 + 0) * 128 + r] = v.x;
            As[(c4 * 4 + 1) * 128 + r] = v.y;
            As[(c4 * 4 + 2) * 128 + r] = v.z;
            As[(c4 * 4 + 3) * 128 + r] = v.w;
        }
        if (TRANSB) {
            // Bs[k][n] = B[n][k]
#pragma unroll
            for (int s = 0; s < 2; s++) {
                int f = tid + 256 * s;
                int r = f >> 2, c4 = f & 3;
                float4 v = *(const float4*)(Bb + (long)(j0 + r) * Kd + kt + c4 * 4);
                Bs[(c4 * 4 + 0) * 128 + r] = v.x;
                Bs[(c4 * 4 + 1) * 128 + r] = v.y;
                Bs[(c4 * 4 + 2) * 128 + r] = v.z;
                Bs[(c4 * 4 + 3) * 128 + r] = v.w;
            }
        } else {
            // Bs[k][n] = B[k][n]
#pragma unroll
            for (int s = 0; s < 2; s++) {
                int f = tid + 256 * s;
                int kr = f >> 5, c4 = f & 31;
                *(float4*)(&Bs[kr * 128 + c4 * 4]) =
                    *(const float4*)(Bb + (long)(kt + kr) * N + j0 + c4 * 4);
            }
        }
        __syncthreads();

#pragma unroll
        for (int kk = 0; kk < 16; kk++) {
            float4 a0 = *(float4*)&As[kk * 128 + ty * 8];
            float4 a1 = *(float4*)&As[kk * 128 + ty * 8 + 4];
            float4 b0 = *(float4*)&Bs[kk * 128 + tx * 8];
            float4 b1 = *(float4*)&Bs[kk * 128 + tx * 8 + 4];
            float a[8] = {a0.x, a0.y, a0.z, a0.w, a1.x, a1.y, a1.z, a1.w};
            float b[8] = {b0.x, b0.y, b0.z, b0.w, b1.x, b1.y, b1.z, b1.w};
#pragma unroll
            for (int i = 0; i < 8; i++)
#pragma unroll
                for (int j = 0; j < 8; j++) acc[i][j] += a[i] * b[j];
        }
        __syncthreads();
    }

    if (EPI == 2) {
#pragma unroll
        for (int i = 0; i < 8; i++) {
            float rm = acc[i][0];
#pragma unroll
            for (int j = 1; j < 8; j++) rm = fmaxf(rm, acc[i][j]);
            rm *= scale;
#pragma unroll
            for (int off = 8; off; off >>= 1)
                rm = fmaxf(rm, __shfl_xor_sync(0xffffffffu, rm, off));
            if (tx == 0)
                atomicMaxF(rowmax + (long)blockIdx.z * rmStride + i0 + ty * 8 + i, rm);
        }
    } else {
        float4 bi0 = *(const float4*)(bias + j0 + tx * 8);
        float4 bi1 = *(const float4*)(bias + j0 + tx * 8 + 4);
        float bb[8] = {bi0.x, bi0.y, bi0.z, bi0.w, bi1.x, bi1.y, bi1.z, bi1.w};
#pragma unroll
        for (int i = 0; i < 8; i++) {
            long row = i0 + ty * 8 + i;
            float c[8];
#pragma unroll
            for (int j = 0; j < 8; j++) {
                float v = acc[i][j] + bb[j];
                c[j] = (EPI == 1) ? gelu_exact(v) : v;
            }
            *(float4*)(Cm + row * (long)N + j0 + tx * 8)     = make_float4(c[0], c[1], c[2], c[3]);
            *(float4*)(Cm + row * (long)N + j0 + tx * 8 + 4) = make_float4(c[4], c[5], c[6], c[7]);
        }
    }
}

// ---------------------------------------------------------------------------
// Top-K per batch via bitonic sort on (score, index), jax tie semantics
// (descending by value, ascending index on ties). Also gathers selected tokens.
// One block per batch, 1024 threads.
// ---------------------------------------------------------------------------
__global__ __launch_bounds__(1024) void topk_kernel(
    const float* __restrict__ scores, const float* __restrict__ sampled,
    float* __restrict__ out_idx, float* __restrict__ out_sel)
{
    __shared__ float sv[NS];
    __shared__ int   si[NS];
    const int b = blockIdx.x;
    const int tid = threadIdx.x;

    for (int i = tid; i < NS; i += 1024) {
        sv[i] = scores[(long)b * NS + i];
        si[i] = i;
    }

    for (int k = 2; k <= NS; k <<= 1) {
        for (int j = k >> 1; j > 0; j >>= 1) {
            __syncthreads();
            for (int i = tid; i < NS; i += 1024) {
                int ixj = i ^ j;
                if (ixj > i) {
                    float v1 = sv[i], v2 = sv[ixj];
                    int a1 = si[i], a2 = si[ixj];
                    // before2: should element at ixj come first in DESC order?
                    bool before2 = (v2 > v1) || (v2 == v1 && a2 < a1);
                    bool up = ((i & k) == 0);
                    if (up ? before2 : !before2) {
                        sv[i] = v2; sv[ixj] = v1;
                        si[i] = a2; si[ixj] = a1;
                    }
                }
            }
        }
    }
    __syncthreads();

    if (tid < TK) out_idx[b * TK + tid] = (float)si[tid];
    for (int e = tid; e < TK * CC; e += 1024) {
        int kk = e / CC, c = e % CC;
        out_sel[(long)b * TK * CC + e] =
            sampled[((long)b * NS + si[kk]) * CC + c];
    }
}

// ---------------------------------------------------------------------------
// Attention: per (row-chunk, h, b). K/V tiles in dynamic smem.
// warp-per-row: logits (4 keys/lane over d=64), softmax, attn out, P·V.
// ---------------------------------------------------------------------------
__global__ __launch_bounds__(256) void attn_kernel(
    const float* __restrict__ q, const float* __restrict__ kbuf,
    const float* __restrict__ vbuf, float* __restrict__ attn_out,
    float* __restrict__ attended)
{
    extern __shared__ float sm[];
    float* kperm = sm;                 // [64][128]: kperm[d][4*(j%32)+(j/32)] = k[j][d]
    float* vs    = sm + 8192;          // [128][64]
    float* qs    = sm + 16384;         // [8][64]
    float* ps    = sm + 16896;         // [8][128]

    const int tid = threadIdx.x;
    const int b = blockIdx.z, h = blockIdx.y;
    const float* kb = kbuf + ((long)b * TK) * CC + h * DH;
    const float* vb = vbuf + ((long)b * TK) * CC + h * DH;

    for (int e = tid; e < TK * DH; e += 256) {
        int j = e >> 6, d = e & 63;
        kperm[d * 128 + 4 * (j & 31) + (j >> 5)] = kb[(long)j * CC + d];
        vs[e] = vb[(long)j * CC + d];
    }
    __syncthreads();

    const int w = tid >> 5, lane = tid & 31;
    for (int it = 0; it < 32; it++) {
        int i = blockIdx.x * 256 + it * 8 + w;
        const float* qrow = q + ((long)(b * NB + i)) * CC + h * DH;
        float2 qv = *(const float2*)(qrow + 2 * lane);
        qs[w * 64 + 2 * lane]     = qv.x;
        qs[w * 64 + 2 * lane + 1] = qv.y;
        __syncwarp();

        float l0 = 0, l1 = 0, l2 = 0, l3 = 0;
#pragma unroll
        for (int d = 0; d < 64; d++) {
            float qd = qs[w * 64 + d];
            float4 k4 = *(const float4*)&kperm[d * 128 + 4 * lane];
            l0 += qd * k4.x; l1 += qd * k4.y; l2 += qd * k4.z; l3 += qd * k4.w;
        }
        l0 *= 0.125f; l1 *= 0.125f; l2 *= 0.125f; l3 *= 0.125f;

        float m = fmaxf(fmaxf(l0, l1), fmaxf(l2, l3));
#pragma unroll
        for (int off = 16; off; off >>= 1)
            m = fmaxf(m, __shfl_xor_sync(0xffffffffu, m, off));
        float p0 = __expf(l0 - m), p1 = __expf(l1 - m);
        float p2 = __expf(l2 - m), p3 = __expf(l3 - m);
        float s = p0 + p1 + p2 + p3;
#pragma unroll
        for (int off = 16; off; off >>= 1)
            s += __shfl_xor_sync(0xffffffffu, s, off);
        float inv = 1.0f / s;
        float a0 = p0 * inv, a1 = p1 * inv, a2 = p2 * inv, a3 = p3 * inv;

        float* ao = attn_out + (((long)(b * HH + h) * NB) + i) * TK;
        ao[lane] = a0; ao[lane + 32] = a1; ao[lane + 64] = a2; ao[lane + 96] = a3;

        ps[w * 128 + lane]      = a0;
        ps[w * 128 + lane + 32] = a1;
        ps[w * 128 + lane + 64] = a2;
        ps[w * 128 + lane + 96] = a3;
        __syncwarp();

        float2 o = make_float2(0.0f, 0.0f);
#pragma unroll
        for (int j = 0; j < 128; j++) {
            float pj = ps[w * 128 + j];
            float2 vv = *(const float2*)&vs[j * 64 + 2 * lane];
            o.x += pj * vv.x; o.y += pj * vv.y;
        }
        float* arow = attended + ((long)(b * NB + i)) * CC + h * DH;
        *(float2*)(arow + 2 * lane) = o;
        __syncwarp();
    }
}

// ---------------------------------------------------------------------------
// Fused residual add + LayerNorm. One warp per row (768 cols, 24 per lane).
// ---------------------------------------------------------------------------
__global__ __launch_bounds__(256) void addln_kernel(
    const float* __restrict__ A, const float* __restrict__ Bv,
    const float* __restrict__ g, const float* __restrict__ beta,
    float* __restrict__ out)
{
    const int w = threadIdx.x >> 5, lane = threadIdx.x & 31;
    const long r = (long)blockIdx.x * 8 + w;
    const float* a = A + r * CC;
    const float* bp = Bv + r * CC;

    float v[24];
    float s = 0.0f, s2 = 0.0f;
#pragma unroll
    for (int t = 0; t < 24; t++) {
        int d = lane + 32 * t;
        float x = a[d] + bp[d];
        v[t] = x; s += x; s2 += x * x;
    }
#pragma unroll
    for (int off = 16; off; off >>= 1) {
        s  += __shfl_xor_sync(0xffffffffu, s, off);
        s2 += __shfl_xor_sync(0xffffffffu, s2, off);
    }
    float mu = s * (1.0f / CC);
    float var = s2 * (1.0f / CC) - mu * mu;
    float rs = rsqrtf(var + 1e-5f);
    float* o = out + r * CC;
#pragma unroll
    for (int t = 0; t < 24; t++) {
        int d = lane + 32 * t;
        o[d] = (v[t] - mu) * rs * g[d] + beta[d];
    }
}

// ---------------------------------------------------------------------------
// launch
// ---------------------------------------------------------------------------
extern "C" void kernel_launch(void* const* d_in, const int* in_sizes, int n_in,
                              void* d_out, int out_size)
{
    const float* base    = (const float*)d_in[0];
    const float* sampled = (const float*)d_in[1];
    const float* Wq = (const float*)d_in[2];  const float* bq = (const float*)d_in[3];
    const float* Wk = (const float*)d_in[4];  const float* bk = (const float*)d_in[5];
    const float* Wv = (const float*)d_in[6];  const float* bv = (const float*)d_in[7];
    const float* Wo = (const float*)d_in[8];  const float* bo = (const float*)d_in[9];
    const float* g1 = (const float*)d_in[10]; const float* b1 = (const float*)d_in[11];
    const float* g2 = (const float*)d_in[12]; const float* b2 = (const float*)d_in[13];
    const float* Wm1 = (const float*)d_in[14]; const float* bm1 = (const float*)d_in[15];
    const float* Wm2 = (const float*)d_in[16]; const float* bm2 = (const float*)d_in[17];

    float* out = (float*)d_out;
    float* out_x      = out;                 // [16,1024,768]
    float* out_scores = out + 12582912;      // [16,4096]
    float* out_attn   = out + 12648448;      // [16,12,1024,128]
    float* out_topk   = out + 37814272;      // [16,128]
    float* out_sel    = out + 37816320;      // [16,128,768]

    float* buf = nullptr;
    cudaGetSymbolAddress((void**)&buf, g_buf);
    float* qb  = buf;
    float* kb  = buf + OFF_K;
    float* vb  = buf + OFF_V;
    float* att = buf + OFF_ATT;
    float* s2  = buf + OFF_S2;
    float* x1  = buf + OFF_X1;
    float* hb  = buf + OFF_H;

    // 1) saliency scores: row-max of (sampled @ base^T)/sqrt(C)
    fill_neg_inf<<<256, 256>>>(out_scores, BN * NS);
    sgemm_kernel<true, 2><<<dim3(NB / 128, NS / 128, BN), 256>>>(
        sampled, base, nullptr, nullptr,
        NB, CC, (long)NS * CC, (long)NB * CC,
        0.03608439182435161f, out_scores, NS);

    // 2) top-k + gather selected
    topk_kernel<<<BN, 1024>>>(out_scores, sampled, out_topk, out_sel);

    // 3) projections
    sgemm_kernel<false, 0><<<dim3(CC / 128, (BN * NB) / 128, 1), 256>>>(
        base, Wq, bq, qb, CC, CC, 0, 0, 1.0f, nullptr, 0);
    sgemm_kernel<false, 0><<<dim3(CC / 128, (BN * TK) / 128, 1), 256>>>(
        out_sel, Wk, bk, kb, CC, CC, 0, 0, 1.0f, nullptr, 0);
    sgemm_kernel<false, 0><<<dim3(CC / 128, (BN * TK) / 128, 1), 256>>>(
        out_sel, Wv, bv, vb, CC, CC, 0, 0, 1.0f, nullptr, 0);

    // 4) attention (softmax + attn output + P·V)
    cudaFuncSetAttribute(attn_kernel, cudaFuncAttributeMaxDynamicSharedMemorySize, 71680);
    attn_kernel<<<dim3(4, HH, BN), 256, 71680>>>(qb, kb, vb, out_attn, att);

    // 5) output projection, residual + LN1
    sgemm_kernel<false, 0><<<dim3(CC / 128, (BN * NB) / 128, 1), 256>>>(
        att, Wo, bo, s2, CC, CC, 0, 0, 1.0f, nullptr, 0);
    addln_kernel<<<(BN * NB) / 8, 256>>>(base, s2, g1, b1, x1);

    // 6) MLP + residual + LN2
    sgemm_kernel<false, 1><<<dim3(CH / 128, (BN * NB) / 128, 1), 256>>>(
        x1, Wm1, bm1, hb, CH, CC, 0, 0, 1.0f, nullptr, 0);
    sgemm_kernel<false, 0><<<dim3(CC / 128, (BN * NB) / 128, 1), 256>>>(
        hb, Wm2, bm2, s2, CC, CH, 0, 0, 1.0f, nullptr, 0);
    addln_kernel<<<(BN * NB) / 8, 256>>>(x1, s2, g2, b2, out_x);
}